// round 14
// baseline (speedup 1.0000x reference)
#include <cuda_runtime.h>
#include <cuda_bf16.h>
#include <cstdint>

// Problem constants (fixed by the dataset)
#define BB 512      // batch
#define TT 512      // timesteps
#define II 128      // sensory inputs
#define UU 64       // LTC units
#define OO 15       // outputs
#define NUNF 4      // ode unfolds
#define LTC_EPS 1e-8f

#define RSYN_REG 48                 // recurrent synapses kept in registers
#define RSYN_SMEM (UU - RSYN_REG)   // recurrent synapses read from smem table (16)

// ---------------- device scratch (allocation-free rule: __device__ globals) ---------
__device__ float4 g_sparam[II * UU];     // sensory per-synapse {a, b, ce, c}
__device__ float4 g_rparam[UU * UU];     // recurrent per-synapse {a, b, ce, c}
__device__ float  g_sKn[UU], g_sKd[UU];  // sensory constant sums
__device__ float  g_cmt[UU], g_numbase[UU], g_denbase[UU];
__device__ float2 g_wns[BB * TT * UU];   // (w_num_s, w_den_s) per (b,t,u)  ~134MB

// ---------------- helpers ------------------------------------------------------------
__device__ __forceinline__ float tanh_fast(float x) {
    float y;
    asm("tanh.approx.f32 %0, %1;" : "=f"(y) : "f"(x));
    return y;
}
// Two tanh for one MUFU op (sensory only).
__device__ __forceinline__ void tanh2_fast(float ax, float ay, float& tx, float& ty) {
    uint32_t h, r;
    asm("cvt.rn.f16x2.f32 %0, %1, %2;" : "=r"(h) : "f"(ay), "f"(ax));
    asm("tanh.approx.f16x2 %0, %1;" : "=r"(r) : "r"(h));
    asm("{\n\t"
        ".reg .b16 lo, hi;\n\t"
        "mov.b32 {lo, hi}, %2;\n\t"
        "cvt.f32.f16 %0, lo;\n\t"
        "cvt.f32.f16 %1, hi;\n\t"
        "}" : "=f"(tx), "=f"(ty) : "r"(r));
}
__device__ __forceinline__ float softplus_f(float x) {
    return log1pf(expf(x));
}

// ---------------- kernel 0a: fold parameters (one thread per synapse) -----------------
// sigmoid(z) = 0.5*tanh(z/2)+0.5; a = 0.5*sigma*iw, b = 0.5*sigma*(ib-mu),
// c = 0.5*sp(w), ce = c*erev (erev = +-1 so c == |ce|).
__global__ void fold_params_kernel(
    const float* __restrict__ iw, const float* __restrict__ ib,
    const float* __restrict__ sw, const float* __restrict__ smu,
    const float* __restrict__ ssig, const float* __restrict__ serev,
    const float* __restrict__ w, const float* __restrict__ mu,
    const float* __restrict__ sig, const float* __restrict__ erev)
{
    int idx = blockIdx.x * blockDim.x + threadIdx.x;
    if (idx < II * UU) {
        int i = idx / UU;
        float c  = 0.5f * softplus_f(sw[idx]);
        float ce = c * serev[idx];
        float a  = 0.5f * ssig[idx] * iw[i];
        float b  = 0.5f * ssig[idx] * (ib[i] - smu[idx]);
        g_sparam[idx] = make_float4(a, b, ce, c);
    }
    int r = idx - II * UU;
    if (r >= 0 && r < UU * UU) {
        float c  = 0.5f * softplus_f(w[r]);
        float ce = c * erev[r];
        float a  = 0.5f * sig[r];
        float b  = -0.5f * sig[r] * mu[r];
        g_rparam[r] = make_float4(a, b, ce, c);
    }
}

// ---------------- kernel 0b: per-neuron constant sums (parallel, 256 threads) ---------
__global__ void fold_neuron_kernel(
    const float* __restrict__ gleak, const float* __restrict__ vleak,
    const float* __restrict__ cm)
{
    __shared__ float part[4][4][UU];
    const int tid = threadIdx.x;
    const int u = tid & 63;
    const int g = tid >> 6;

    float skn = 0.f, skd = 0.f;
#pragma unroll 4
    for (int i = g * 32; i < g * 32 + 32; i++) {
        float4 p = g_sparam[i * UU + u];
        skn += p.z; skd += p.w;
    }
    float rkn = 0.f, rkd = 0.f;
#pragma unroll 4
    for (int j = g * 16; j < g * 16 + 16; j++) {
        float4 p = g_rparam[j * UU + u];
        rkn += p.z; rkd += p.w;
    }
    part[g][0][u] = skn; part[g][1][u] = skd;
    part[g][2][u] = rkn; part[g][3][u] = rkd;
    __syncthreads();
    if (g == 0) {
        skn = part[0][0][u] + part[1][0][u] + part[2][0][u] + part[3][0][u];
        skd = part[0][1][u] + part[1][1][u] + part[2][1][u] + part[3][1][u];
        rkn = part[0][2][u] + part[1][2][u] + part[2][2][u] + part[3][2][u];
        rkd = part[0][3][u] + part[1][3][u] + part[2][3][u] + part[3][3][u];
        g_sKn[u] = skn;
        g_sKd[u] = skd;
        float gp  = softplus_f(gleak[u]);
        float cmt = (float)NUNF * softplus_f(cm[u]);
        g_cmt[u]     = cmt;
        g_numbase[u] = gp * vleak[u] + rkn;
        g_denbase[u] = cmt + gp + rkd + LTC_EPS;
    }
}

// ---------------- kernel 1: sensory synapse sums over all (b,t) ----------------------
// R13 version (best measured): barrier-free, no smem, FOUR rows per iteration,
// f16x2 tanh over row pairs. 512 threads: u = tid>>3, ig = tid&7.
#define ROWS_PER_BLOCK 128
__global__ __launch_bounds__(512, 1) void sensory_kernel(const float* __restrict__ x)
{
    const int tid = threadIdx.x;
    const int u  = tid >> 3;
    const int ig = tid & 7;

    float pa[16], pb[16], pce[16];
#pragma unroll
    for (int ii = 0; ii < 16; ii++) {
        float4 p = g_sparam[(ig * 16 + ii) * UU + u];
        pa[ii] = p.x; pb[ii] = p.y; pce[ii] = p.z;
    }
    const float kn = g_sKn[u];
    const float kd = g_sKd[u];

    const size_t base_row = (size_t)blockIdx.x * ROWS_PER_BLOCK;
    const float4* __restrict__ xr = (const float4*)x + base_row * (II / 4) + ig * 4;

    for (int r = 0; r < ROWS_PER_BLOCK; r += 4) {
        float4 xv[4][4];
#pragma unroll
        for (int rr = 0; rr < 4; rr++)
#pragma unroll
            for (int q = 0; q < 4; q++)
                xv[rr][q] = xr[(size_t)(r + rr) * (II / 4) + q];

        float pn[4] = {0.f, 0.f, 0.f, 0.f};
        float pd[4] = {0.f, 0.f, 0.f, 0.f};
#pragma unroll
        for (int q = 0; q < 4; q++) {
            const int s = q * 4;
#pragma unroll
            for (int e = 0; e < 4; e++) {
                const float av = pa[s + e], bv = pb[s + e];
                const float ce = pce[s + e];
                const float c  = fabsf(ce);
                float xa0 = fmaf(av, ((const float*)&xv[0][q])[e], bv);
                float xa1 = fmaf(av, ((const float*)&xv[1][q])[e], bv);
                float xa2 = fmaf(av, ((const float*)&xv[2][q])[e], bv);
                float xa3 = fmaf(av, ((const float*)&xv[3][q])[e], bv);
                float t0, t1, t2, t3;
                tanh2_fast(xa0, xa1, t0, t1);
                tanh2_fast(xa2, xa3, t2, t3);
                pn[0] = fmaf(ce, t0, pn[0]);  pd[0] = fmaf(c, t0, pd[0]);
                pn[1] = fmaf(ce, t1, pn[1]);  pd[1] = fmaf(c, t1, pd[1]);
                pn[2] = fmaf(ce, t2, pn[2]);  pd[2] = fmaf(c, t2, pd[2]);
                pn[3] = fmaf(ce, t3, pn[3]);  pd[3] = fmaf(c, t3, pd[3]);
            }
        }
#pragma unroll
        for (int o = 1; o <= 4; o <<= 1) {
#pragma unroll
            for (int rr = 0; rr < 4; rr++) {
                pn[rr] += __shfl_xor_sync(0xffffffffu, pn[rr], o);
                pd[rr] += __shfl_xor_sync(0xffffffffu, pd[rr], o);
            }
        }
        if (ig == 0) {
#pragma unroll
            for (int rr = 0; rr < 4; rr++)
                __stcg(&g_wns[(base_row + r + rr) * UU + u],
                       make_float2(pn[rr] + kn, pd[rr] + kd));
        }
    }
}

// ---------------- kernel 2: sequential scan + LayerNorm + FC head --------------------
// R3 structure (one 64-thread block per batch, thread u owns unit u, local division)
// with the 48/16 anti-spill split: 48 synapses' params in registers (144 regs, NO
// spill), 16 synapses' params in a 16KB smem table ptab[j][u] (lane==u -> conflict-
// free LDS.128; 16 LDS.128/unfold hidden under the 512-cyc MUFU burst).
__global__ __launch_bounds__(64, 4) void scan_kernel(
    const float* __restrict__ outw, const float* __restrict__ outb,
    const float* __restrict__ lnw,  const float* __restrict__ lnb,
    const float* __restrict__ fcw,  const float* __restrict__ fcb,
    float* __restrict__ out)
{
    __shared__ float4 vsm4[2][UU / 4];
    __shared__ float  stats[2];
    __shared__ float  hbuf[UU];
    __shared__ float4 ptab[RSYN_SMEM][UU];   // {a,b,ce,c} for j = 48..63 (16KB)

    const int u = threadIdx.x;        // 0..63 : unit owned by this thread
    const int b = blockIdx.x;

    // cooperative load of the smem param table (1024 float4 / 64 threads)
#pragma unroll
    for (int q = u; q < RSYN_SMEM * UU; q += 64)
        ((float4*)ptab)[q] = g_rparam[RSYN_REG * UU + q];

    float ra[RSYN_REG], rb[RSYN_REG], rce[RSYN_REG];
#pragma unroll
    for (int j = 0; j < RSYN_REG; j++) {
        float4 p = g_rparam[j * UU + u];
        ra[j] = p.x; rb[j] = p.y; rce[j] = p.z;
    }
    const float cmtu = g_cmt[u];
    const float nb   = g_numbase[u];
    const float db   = g_denbase[u];

    ((float*)vsm4[0])[u] = 0.f;
    float vu = 0.f;
    __syncthreads();

    const float2* __restrict__ wns = g_wns + (size_t)b * TT * UU;
    float2 wnd = __ldcg(&wns[u]);

    for (int t = 0; t < TT; t++) {
        float2 wnd_n = (t + 1 < TT) ? __ldcg(&wns[(t + 1) * UU + u])
                                    : make_float2(0.f, 0.f);
#pragma unroll
        for (int k = 0; k < NUNF; k++) {
            const float4* vr4 = vsm4[k & 1];
            float pn = 0.f, pd = 0.f;
            // register-resident synapses 0..47
#pragma unroll
            for (int q = 0; q < RSYN_REG / 4; q++) {
                float4 v4 = vr4[q];
                const int s = q * 4;
                float t0 = tanh_fast(fmaf(ra[s + 0], v4.x, rb[s + 0]));
                float t1 = tanh_fast(fmaf(ra[s + 1], v4.y, rb[s + 1]));
                float t2 = tanh_fast(fmaf(ra[s + 2], v4.z, rb[s + 2]));
                float t3 = tanh_fast(fmaf(ra[s + 3], v4.w, rb[s + 3]));
                pn = fmaf(rce[s + 0], t0, pn);  pd = fmaf(fabsf(rce[s + 0]), t0, pd);
                pn = fmaf(rce[s + 1], t1, pn);  pd = fmaf(fabsf(rce[s + 1]), t1, pd);
                pn = fmaf(rce[s + 2], t2, pn);  pd = fmaf(fabsf(rce[s + 2]), t2, pd);
                pn = fmaf(rce[s + 3], t3, pn);  pd = fmaf(fabsf(rce[s + 3]), t3, pd);
            }
            // smem-resident synapses 48..63 (conflict-free: lane index == u)
#pragma unroll
            for (int q = RSYN_REG / 4; q < UU / 4; q++) {
                float4 v4 = vr4[q];
                const float vv[4] = {v4.x, v4.y, v4.z, v4.w};
                const int sj = q * 4 - RSYN_REG;
#pragma unroll
                for (int e = 0; e < 4; e++) {
                    float4 pp = ptab[sj + e][u];
                    float th = tanh_fast(fmaf(pp.x, vv[e], pp.y));
                    pn = fmaf(pp.z, th, pn);
                    pd = fmaf(pp.w, th, pd);
                }
            }
            float num = fmaf(cmtu, vu, nb) + wnd.x + pn;
            float den = db + wnd.y + pd;
            vu = __fdividef(num, den);
            ((float*)vsm4[(k & 1) ^ 1])[u] = vu;
            __syncthreads();
        }
        wnd = wnd_n;
    }

    // ----- head: h = v*ow + ob; LayerNorm(eps=1e-5); out = h @ fc_w^T + fc_b -----
    float h = fmaf(vu, outw[u], outb[u]);
    hbuf[u] = h;
    __syncthreads();
    if (u < 32) {
        float a = hbuf[u] + hbuf[u + 32];
        float q = hbuf[u] * hbuf[u] + hbuf[u + 32] * hbuf[u + 32];
#pragma unroll
        for (int o = 16; o > 0; o >>= 1) {
            a += __shfl_down_sync(0xffffffffu, a, o);
            q += __shfl_down_sync(0xffffffffu, q, o);
        }
        if (u == 0) {
            float mean = a * (1.0f / UU);
            float var  = q * (1.0f / UU) - mean * mean;
            stats[0] = mean;
            stats[1] = rsqrtf(var + 1e-5f);
        }
    }
    __syncthreads();
    hbuf[u] = fmaf((h - stats[0]) * stats[1], lnw[u], lnb[u]);
    __syncthreads();
    if (u < OO) {
        float acc = fcb[u];
#pragma unroll
        for (int uu = 0; uu < UU; uu++)
            acc = fmaf(hbuf[uu], fcw[u * UU + uu], acc);
        out[b * OO + u] = acc;
    }
}

// ---------------- launch --------------------------------------------------------------
extern "C" void kernel_launch(void* const* d_in, const int* in_sizes, int n_in,
                              void* d_out, int out_size)
{
    const float* x     = (const float*)d_in[0];
    const float* iw    = (const float*)d_in[1];
    const float* ibv   = (const float*)d_in[2];
    const float* sw    = (const float*)d_in[3];
    const float* smu   = (const float*)d_in[4];
    const float* ssig  = (const float*)d_in[5];
    const float* serev = (const float*)d_in[6];
    const float* w     = (const float*)d_in[7];
    const float* mu    = (const float*)d_in[8];
    const float* sig   = (const float*)d_in[9];
    const float* erev  = (const float*)d_in[10];
    const float* gleak = (const float*)d_in[11];
    const float* vleak = (const float*)d_in[12];
    const float* cm    = (const float*)d_in[13];
    const float* outw  = (const float*)d_in[14];
    const float* outb  = (const float*)d_in[15];
    const float* lnw   = (const float*)d_in[16];
    const float* lnb   = (const float*)d_in[17];
    const float* fcw   = (const float*)d_in[18];
    const float* fcb   = (const float*)d_in[19];
    float* out = (float*)d_out;

    const int n_syn = II * UU + UU * UU;           // 12288
    fold_params_kernel<<<(n_syn + 255) / 256, 256>>>(iw, ibv, sw, smu, ssig, serev,
                                                     w, mu, sig, erev);
    fold_neuron_kernel<<<1, 256>>>(gleak, vleak, cm);

    int nblocks = (BB * TT) / ROWS_PER_BLOCK;      // 2048
    sensory_kernel<<<nblocks, 512>>>(x);

    scan_kernel<<<BB, 64>>>(outw, outb, lnw, lnb, fcw, fcb, out);
}

// round 15
// speedup vs baseline: 1.0412x; 1.0412x over previous
#include <cuda_runtime.h>
#include <cuda_bf16.h>
#include <cstdint>

// Problem constants (fixed by the dataset)
#define BB 512      // batch
#define TT 512      // timesteps
#define II 128      // sensory inputs
#define UU 64       // LTC units
#define OO 15       // outputs
#define NUNF 4      // ode unfolds
#define LTC_EPS 1e-8f

// ---------------- device scratch (allocation-free rule: __device__ globals) ---------
__device__ float4 g_sparam[II * UU];     // sensory per-synapse {a, b, ce, c}
__device__ float4 g_rparam[UU * UU];     // recurrent per-synapse {a, b, ce, c}
__device__ float  g_sKn[UU], g_sKd[UU];  // sensory constant sums
__device__ float  g_cmt[UU], g_numbase[UU], g_denbase[UU];
__device__ float2 g_wns[BB * TT * UU];   // (w_num_s, w_den_s) per (b,t,u)  ~134MB

// ---------------- helpers ------------------------------------------------------------
__device__ __forceinline__ float tanh_fast(float x) {
    float y;
    asm("tanh.approx.f32 %0, %1;" : "=f"(y) : "f"(x));
    return y;
}
// Two tanh for one MUFU op (sensory only).
__device__ __forceinline__ void tanh2_fast(float ax, float ay, float& tx, float& ty) {
    uint32_t h, r;
    asm("cvt.rn.f16x2.f32 %0, %1, %2;" : "=r"(h) : "f"(ay), "f"(ax));
    asm("tanh.approx.f16x2 %0, %1;" : "=r"(r) : "r"(h));
    asm("{\n\t"
        ".reg .b16 lo, hi;\n\t"
        "mov.b32 {lo, hi}, %2;\n\t"
        "cvt.f32.f16 %0, lo;\n\t"
        "cvt.f32.f16 %1, hi;\n\t"
        "}" : "=f"(tx), "=f"(ty) : "r"(r));
}
__device__ __forceinline__ float softplus_f(float x) {
    return log1pf(expf(x));
}

// ---------------- kernel 0a: fold parameters (one thread per synapse) -----------------
// sigmoid(z) = 0.5*tanh(z/2)+0.5; a = 0.5*sigma*iw, b = 0.5*sigma*(ib-mu),
// c = 0.5*sp(w), ce = c*erev (erev = +-1 so c == |ce|).
__global__ void fold_params_kernel(
    const float* __restrict__ iw, const float* __restrict__ ib,
    const float* __restrict__ sw, const float* __restrict__ smu,
    const float* __restrict__ ssig, const float* __restrict__ serev,
    const float* __restrict__ w, const float* __restrict__ mu,
    const float* __restrict__ sig, const float* __restrict__ erev)
{
    int idx = blockIdx.x * blockDim.x + threadIdx.x;
    if (idx < II * UU) {
        int i = idx / UU;
        float c  = 0.5f * softplus_f(sw[idx]);
        float ce = c * serev[idx];
        float a  = 0.5f * ssig[idx] * iw[i];
        float b  = 0.5f * ssig[idx] * (ib[i] - smu[idx]);
        g_sparam[idx] = make_float4(a, b, ce, c);
    }
    int r = idx - II * UU;
    if (r >= 0 && r < UU * UU) {
        float c  = 0.5f * softplus_f(w[r]);
        float ce = c * erev[r];
        float a  = 0.5f * sig[r];
        float b  = -0.5f * sig[r] * mu[r];
        g_rparam[r] = make_float4(a, b, ce, c);
    }
}

// ---------------- kernel 0b: per-neuron constant sums (parallel, 256 threads) ---------
__global__ void fold_neuron_kernel(
    const float* __restrict__ gleak, const float* __restrict__ vleak,
    const float* __restrict__ cm)
{
    __shared__ float part[4][4][UU];
    const int tid = threadIdx.x;
    const int u = tid & 63;
    const int g = tid >> 6;

    float skn = 0.f, skd = 0.f;
#pragma unroll 4
    for (int i = g * 32; i < g * 32 + 32; i++) {
        float4 p = g_sparam[i * UU + u];
        skn += p.z; skd += p.w;
    }
    float rkn = 0.f, rkd = 0.f;
#pragma unroll 4
    for (int j = g * 16; j < g * 16 + 16; j++) {
        float4 p = g_rparam[j * UU + u];
        rkn += p.z; rkd += p.w;
    }
    part[g][0][u] = skn; part[g][1][u] = skd;
    part[g][2][u] = rkn; part[g][3][u] = rkd;
    __syncthreads();
    if (g == 0) {
        skn = part[0][0][u] + part[1][0][u] + part[2][0][u] + part[3][0][u];
        skd = part[0][1][u] + part[1][1][u] + part[2][1][u] + part[3][1][u];
        rkn = part[0][2][u] + part[1][2][u] + part[2][2][u] + part[3][2][u];
        rkd = part[0][3][u] + part[1][3][u] + part[2][3][u] + part[3][3][u];
        g_sKn[u] = skn;
        g_sKd[u] = skd;
        float gp  = softplus_f(gleak[u]);
        float cmt = (float)NUNF * softplus_f(cm[u]);
        g_cmt[u]     = cmt;
        g_numbase[u] = gp * vleak[u] + rkn;
        g_denbase[u] = cmt + gp + rkd + LTC_EPS;
    }
}

// ---------------- kernel 1: sensory synapse sums over all (b,t) ----------------------
// R13 version (best measured): barrier-free, no smem, FOUR rows per iteration,
// f16x2 tanh over row pairs. 512 threads: u = tid>>3, ig = tid&7.
// Store tail spread across ig 0 and 1 (reduced values are identical in all lanes
// after the full xor-reduction).
#define ROWS_PER_BLOCK 128
__global__ __launch_bounds__(512, 1) void sensory_kernel(const float* __restrict__ x)
{
    const int tid = threadIdx.x;
    const int u  = tid >> 3;
    const int ig = tid & 7;

    float pa[16], pb[16], pce[16];
#pragma unroll
    for (int ii = 0; ii < 16; ii++) {
        float4 p = g_sparam[(ig * 16 + ii) * UU + u];
        pa[ii] = p.x; pb[ii] = p.y; pce[ii] = p.z;
    }
    const float kn = g_sKn[u];
    const float kd = g_sKd[u];

    const size_t base_row = (size_t)blockIdx.x * ROWS_PER_BLOCK;
    const float4* __restrict__ xr = (const float4*)x + base_row * (II / 4) + ig * 4;

    for (int r = 0; r < ROWS_PER_BLOCK; r += 4) {
        float4 xv[4][4];
#pragma unroll
        for (int rr = 0; rr < 4; rr++)
#pragma unroll
            for (int q = 0; q < 4; q++)
                xv[rr][q] = xr[(size_t)(r + rr) * (II / 4) + q];

        float pn[4] = {0.f, 0.f, 0.f, 0.f};
        float pd[4] = {0.f, 0.f, 0.f, 0.f};
#pragma unroll
        for (int q = 0; q < 4; q++) {
            const int s = q * 4;
#pragma unroll
            for (int e = 0; e < 4; e++) {
                const float av = pa[s + e], bv = pb[s + e];
                const float ce = pce[s + e];
                const float c  = fabsf(ce);
                float xa0 = fmaf(av, ((const float*)&xv[0][q])[e], bv);
                float xa1 = fmaf(av, ((const float*)&xv[1][q])[e], bv);
                float xa2 = fmaf(av, ((const float*)&xv[2][q])[e], bv);
                float xa3 = fmaf(av, ((const float*)&xv[3][q])[e], bv);
                float t0, t1, t2, t3;
                tanh2_fast(xa0, xa1, t0, t1);
                tanh2_fast(xa2, xa3, t2, t3);
                pn[0] = fmaf(ce, t0, pn[0]);  pd[0] = fmaf(c, t0, pd[0]);
                pn[1] = fmaf(ce, t1, pn[1]);  pd[1] = fmaf(c, t1, pd[1]);
                pn[2] = fmaf(ce, t2, pn[2]);  pd[2] = fmaf(c, t2, pd[2]);
                pn[3] = fmaf(ce, t3, pn[3]);  pd[3] = fmaf(c, t3, pd[3]);
            }
        }
#pragma unroll
        for (int o = 1; o <= 4; o <<= 1) {
#pragma unroll
            for (int rr = 0; rr < 4; rr++) {
                pn[rr] += __shfl_xor_sync(0xffffffffu, pn[rr], o);
                pd[rr] += __shfl_xor_sync(0xffffffffu, pd[rr], o);
            }
        }
        // after xor-reduction every lane holds the full sums: split stores over ig 0/1
        if (ig < 2) {
#pragma unroll
            for (int rr = 0; rr < 2; rr++) {
                int row = ig * 2 + rr;
                __stcg(&g_wns[(base_row + r + row) * UU + u],
                       make_float2(pn[row] + kn, pd[row] + kd));
            }
        }
    }
}

// ---------------- kernel 2: sequential scan + LayerNorm + FC head (R3 verbatim) ------
// One block (64 threads = 2 warps) per batch. Thread u owns unit u completely:
// all 64 recurrent synapse params in registers, local accumulation, local division.
// Best measured: 1.298/1.301 ms across two runs. Register-file-bound (4 blocks/SM
// x 64 thr x 255 regs = whole RF); occupancy cannot rise for this decomposition.
__global__ __launch_bounds__(64, 4) void scan_kernel(
    const float* __restrict__ outw, const float* __restrict__ outb,
    const float* __restrict__ lnw,  const float* __restrict__ lnb,
    const float* __restrict__ fcw,  const float* __restrict__ fcb,
    float* __restrict__ out)
{
    __shared__ float4 vsm4[2][UU / 4];
    __shared__ float  stats[2];
    __shared__ float  hbuf[UU];

    const int u = threadIdx.x;        // 0..63 : unit owned by this thread
    const int b = blockIdx.x;

    float ra[UU], rb[UU], rce[UU];
#pragma unroll
    for (int j = 0; j < UU; j++) {
        float4 p = g_rparam[j * UU + u];
        ra[j] = p.x; rb[j] = p.y; rce[j] = p.z;
    }
    const float cmtu = g_cmt[u];
    const float nb   = g_numbase[u];
    const float db   = g_denbase[u];

    ((float*)vsm4[0])[u] = 0.f;
    float vu = 0.f;
    __syncthreads();

    const float2* __restrict__ wns = g_wns + (size_t)b * TT * UU;
    float2 wnd = __ldcg(&wns[u]);

    for (int t = 0; t < TT; t++) {
        float2 wnd_n = (t + 1 < TT) ? __ldcg(&wns[(t + 1) * UU + u])
                                    : make_float2(0.f, 0.f);
#pragma unroll
        for (int k = 0; k < NUNF; k++) {
            const float4* vr4 = vsm4[k & 1];
            float pn = 0.f, pd = 0.f;
#pragma unroll
            for (int q = 0; q < UU / 4; q++) {
                float4 v4 = vr4[q];
                const int s = q * 4;
                float t0 = tanh_fast(fmaf(ra[s + 0], v4.x, rb[s + 0]));
                float t1 = tanh_fast(fmaf(ra[s + 1], v4.y, rb[s + 1]));
                float t2 = tanh_fast(fmaf(ra[s + 2], v4.z, rb[s + 2]));
                float t3 = tanh_fast(fmaf(ra[s + 3], v4.w, rb[s + 3]));
                pn = fmaf(rce[s + 0], t0, pn);  pd = fmaf(fabsf(rce[s + 0]), t0, pd);
                pn = fmaf(rce[s + 1], t1, pn);  pd = fmaf(fabsf(rce[s + 1]), t1, pd);
                pn = fmaf(rce[s + 2], t2, pn);  pd = fmaf(fabsf(rce[s + 2]), t2, pd);
                pn = fmaf(rce[s + 3], t3, pn);  pd = fmaf(fabsf(rce[s + 3]), t3, pd);
            }
            float num = fmaf(cmtu, vu, nb) + wnd.x + pn;
            float den = db + wnd.y + pd;
            vu = __fdividef(num, den);
            ((float*)vsm4[(k & 1) ^ 1])[u] = vu;
            __syncthreads();
        }
        wnd = wnd_n;
    }

    // ----- head: h = v*ow + ob; LayerNorm(eps=1e-5); out = h @ fc_w^T + fc_b -----
    float h = fmaf(vu, outw[u], outb[u]);
    hbuf[u] = h;
    __syncthreads();
    if (u < 32) {
        float a = hbuf[u] + hbuf[u + 32];
        float q = hbuf[u] * hbuf[u] + hbuf[u + 32] * hbuf[u + 32];
#pragma unroll
        for (int o = 16; o > 0; o >>= 1) {
            a += __shfl_down_sync(0xffffffffu, a, o);
            q += __shfl_down_sync(0xffffffffu, q, o);
        }
        if (u == 0) {
            float mean = a * (1.0f / UU);
            float var  = q * (1.0f / UU) - mean * mean;
            stats[0] = mean;
            stats[1] = rsqrtf(var + 1e-5f);
        }
    }
    __syncthreads();
    hbuf[u] = fmaf((h - stats[0]) * stats[1], lnw[u], lnb[u]);
    __syncthreads();
    if (u < OO) {
        float acc = fcb[u];
#pragma unroll
        for (int uu = 0; uu < UU; uu++)
            acc = fmaf(hbuf[uu], fcw[u * UU + uu], acc);
        out[b * OO + u] = acc;
    }
}

// ---------------- launch --------------------------------------------------------------
extern "C" void kernel_launch(void* const* d_in, const int* in_sizes, int n_in,
                              void* d_out, int out_size)
{
    const float* x     = (const float*)d_in[0];
    const float* iw    = (const float*)d_in[1];
    const float* ibv   = (const float*)d_in[2];
    const float* sw    = (const float*)d_in[3];
    const float* smu   = (const float*)d_in[4];
    const float* ssig  = (const float*)d_in[5];
    const float* serev = (const float*)d_in[6];
    const float* w     = (const float*)d_in[7];
    const float* mu    = (const float*)d_in[8];
    const float* sig   = (const float*)d_in[9];
    const float* erev  = (const float*)d_in[10];
    const float* gleak = (const float*)d_in[11];
    const float* vleak = (const float*)d_in[12];
    const float* cm    = (const float*)d_in[13];
    const float* outw  = (const float*)d_in[14];
    const float* outb  = (const float*)d_in[15];
    const float* lnw   = (const float*)d_in[16];
    const float* lnb   = (const float*)d_in[17];
    const float* fcw   = (const float*)d_in[18];
    const float* fcb   = (const float*)d_in[19];
    float* out = (float*)d_out;

    const int n_syn = II * UU + UU * UU;           // 12288
    fold_params_kernel<<<(n_syn + 255) / 256, 256>>>(iw, ibv, sw, smu, ssig, serev,
                                                     w, mu, sig, erev);
    fold_neuron_kernel<<<1, 256>>>(gleak, vleak, cm);

    int nblocks = (BB * TT) / ROWS_PER_BLOCK;      // 2048
    sensory_kernel<<<nblocks, 512>>>(x);

    scan_kernel<<<BB, 64>>>(outw, outb, lnw, lnb, fcw, fcb, out);
}